// round 16
// baseline (speedup 1.0000x reference)
#include <cuda_runtime.h>
#include <cuda_fp16.h>

#define NBODY 4194304
#define NMASK (NBODY / 32)
#define MAXPART 16384
#define NS1 32
#define HALF_PI 1.57079632679489662f

// Scratch — __device__ globals. g_cnt zero at load; KB re-zeroes it each call.
// g_rec/g_mask/g_part/g_p2 fully overwritten each call. Replay-safe.
__device__ unsigned int g_cnt[NBODY];    // per-body endpoint counts
__device__ unsigned int g_rec[NBODY];    // {f16 ax | f16 ay}
__device__ unsigned int g_mask[NMASK];   // touched bitmask (1 bit/body)
__device__ float4       g_part[MAXPART]; // per-block partial sums
__device__ double4      g_p2[NS1];       // stage-1 reduced partials
__device__ float4       g_target;        // {tx, ty, stiffness*DT, 0}

// ---------------------------------------------------------------------------
// KA (fused, R4 shape — measured 38.1 us there with MORE traffic):
// thread b builds record for body b (coalesced stream) AND issues one
// fire-and-forget RED.ADD.u32 for endpoint b of concat(from,to). The random
// L2 atomics hide under the DRAM-bound streaming.
// ---------------------------------------------------------------------------
__global__ void __launch_bounds__(256)
ka_build_scatter(const float2* __restrict__ pos,
                 const float*  __restrict__ ang,
                 const float2* __restrict__ fpos,
                 const float2* __restrict__ tpos,
                 const int*    __restrict__ fromb,
                 const int*    __restrict__ tob,
                 int n, int nc) {
    int b = blockIdx.x * blockDim.x + threadIdx.x;

    if (b < n) {
        float2 p = pos[b];
        float  a = ang[b] - HALF_PI;
        // rel = concat(from_pos, to_pos), indexed by BODY index
        float2 r = (b < nc) ? fpos[b] : tpos[b - nc];

        float s, c;
        __sincosf(a, &s, &c);
        float ax = fmaf(c, r.x, fmaf(-s, r.y, p.x));
        float ay = fmaf(s, r.x, fmaf( c, r.y, p.y));

        g_rec[b] = (unsigned int)__half_as_ushort(__float2half_rn(ax))
                 | ((unsigned int)__half_as_ushort(__float2half_rn(ay)) << 16);
    }

    // endpoint b of the concatenated index list (2*nc endpoints total)
    if (b < 2 * nc) {
        int e = (b < nc) ? fromb[b] : tob[b - nc];
        atomicAdd(&g_cnt[e], 1u);   // return unused -> RED (fire-and-forget)
    }
}

// ---------------------------------------------------------------------------
// KB: cnt-dependent pass, 1 body/thread. Read cnt, zero it (replay state),
// ballot the touched bit into the 0.5 MB bitmask, block-reduce
// cnt*m*{ax,ay,1} into ONE plain float4 partial per block. No atomics.
// ---------------------------------------------------------------------------
__global__ void __launch_bounds__(256)
kb_sums(const float* __restrict__ mass, int n) {
    int b = blockIdx.x * blockDim.x + threadIdx.x;
    bool in = (b < n);

    unsigned int cnt = 0u;
    if (in) {
        cnt = g_cnt[b];
        g_cnt[b] = 0u;                       // restore replay state
    }

    // warp ballot: 32 lanes = 32 consecutive bodies = one mask word
    unsigned int bal = __ballot_sync(0xffffffffu, in && cnt != 0u);
    if ((threadIdx.x & 31) == 0 && in) g_mask[b >> 5] = bal;

    float sx = 0.0f, sy = 0.0f, sm = 0.0f;
    if (in) {
        unsigned int rc = g_rec[b];
        float ax = __half2float(__ushort_as_half((unsigned short)(rc & 0xffffu)));
        float ay = __half2float(__ushort_as_half((unsigned short)(rc >> 16)));
        float cm = (float)cnt * mass[b];
        sx = cm * ax;
        sy = cm * ay;
        sm = cm;
    }

    #pragma unroll
    for (int o = 16; o > 0; o >>= 1) {
        sx += __shfl_down_sync(0xffffffffu, sx, o);
        sy += __shfl_down_sync(0xffffffffu, sy, o);
        sm += __shfl_down_sync(0xffffffffu, sm, o);
    }

    __shared__ float ssx[8], ssy[8], ssm[8];
    int wid = threadIdx.x >> 5, lid = threadIdx.x & 31;
    if (lid == 0) { ssx[wid] = sx; ssy[wid] = sy; ssm[wid] = sm; }
    __syncthreads();

    if (threadIdx.x == 0) {
        float tx = 0.0f, ty = 0.0f, tm = 0.0f;
        #pragma unroll
        for (int w = 0; w < 8; ++w) { tx += ssx[w]; ty += ssy[w]; tm += ssm[w]; }
        g_part[blockIdx.x] = make_float4(tx, ty, tm, 0.0f);   // plain store
    }
}

// ---------------------------------------------------------------------------
// KC stage 1: 32 blocks x 256 threads reduce the partials in parallel.
// (Verbatim from the 84.0 us build.)
// ---------------------------------------------------------------------------
__global__ void __launch_bounds__(256)
kc_stage1(int nparts) {
    int chunk = (nparts + NS1 - 1) / NS1;
    int base  = blockIdx.x * chunk;
    int end   = base + chunk; if (end > nparts) end = nparts;

    double sx = 0.0, sy = 0.0, sm = 0.0;
    for (int i = base + threadIdx.x; i < end; i += 256) {
        float4 p = g_part[i];
        sx += (double)p.x; sy += (double)p.y; sm += (double)p.z;
    }

    #pragma unroll
    for (int o = 16; o > 0; o >>= 1) {
        sx += __shfl_down_sync(0xffffffffu, sx, o);
        sy += __shfl_down_sync(0xffffffffu, sy, o);
        sm += __shfl_down_sync(0xffffffffu, sm, o);
    }
    __shared__ double dsx[8], dsy[8], dsm[8];
    int wid = threadIdx.x >> 5, lid = threadIdx.x & 31;
    if (lid == 0) { dsx[wid] = sx; dsy[wid] = sy; dsm[wid] = sm; }
    __syncthreads();
    if (threadIdx.x == 0) {
        double tx = 0.0, ty = 0.0, tm = 0.0;
        #pragma unroll
        for (int w = 0; w < 8; ++w) { tx += dsx[w]; ty += dsy[w]; tm += dsm[w]; }
        g_p2[blockIdx.x] = make_double4(tx, ty, tm, 0.0);
    }
}

// ---------------------------------------------------------------------------
// KC stage 2: one warp reduces the 32 stage-1 partials, writes g_target.
// (Verbatim from the 84.0 us build.)
// ---------------------------------------------------------------------------
__global__ void __launch_bounds__(32)
kc_stage2(const float* __restrict__ stiff) {
    int lid = threadIdx.x;
    double4 p = g_p2[lid];
    double sx = p.x, sy = p.y, sm = p.z;
    #pragma unroll
    for (int o = 16; o > 0; o >>= 1) {
        sx += __shfl_down_sync(0xffffffffu, sx, o);
        sy += __shfl_down_sync(0xffffffffu, sy, o);
        sm += __shfl_down_sync(0xffffffffu, sm, o);
    }
    if (lid == 0)
        g_target = make_float4((float)(sx / sm), (float)(sy / sm),
                               stiff[0] * 0.01f, 0.0f);
}

// ---------------------------------------------------------------------------
// K3: vectorized mask-epilogue, 2 bodies/thread (measured 13.2 us in R8).
// ---------------------------------------------------------------------------
__global__ void __launch_bounds__(256)
k3_apply(const float4* __restrict__ vel2,
         float4*       __restrict__ out2,
         int nhalf) {
    int i = blockIdx.x * blockDim.x + threadIdx.x;
    if (i >= nhalf) return;

    float4 t = g_target;                         // uniform broadcast
    unsigned int mw = g_mask[i >> 4];            // word for bodies 2i, 2i+1
    uint2  rc = ((const uint2*)g_rec)[i];
    float4 v  = vel2[i];

    int bit0 = (2 * i) & 31;
    {
        float ax = __half2float(__ushort_as_half((unsigned short)(rc.x & 0xffffu)));
        float ay = __half2float(__ushort_as_half((unsigned short)(rc.x >> 16)));
        float f  = ((mw >> bit0) & 1u) ? t.z : 0.0f;
        v.x = fmaf(f, t.x - ax, v.x);
        v.y = fmaf(f, t.y - ay, v.y);
    }
    {
        float ax = __half2float(__ushort_as_half((unsigned short)(rc.y & 0xffffu)));
        float ay = __half2float(__ushort_as_half((unsigned short)(rc.y >> 16)));
        float f  = ((mw >> (bit0 + 1)) & 1u) ? t.z : 0.0f;
        v.z = fmaf(f, t.x - ax, v.z);
        v.w = fmaf(f, t.y - ay, v.w);
    }
    out2[i] = v;
}

__global__ void __launch_bounds__(256)
k3_apply_tail(const float2* __restrict__ vel,
              float2*       __restrict__ out,
              int start, int n) {
    int b = start + blockIdx.x * blockDim.x + threadIdx.x;
    if (b >= n) return;
    float4 t = g_target;
    unsigned int rc = g_rec[b];
    float ax = __half2float(__ushort_as_half((unsigned short)(rc & 0xffffu)));
    float ay = __half2float(__ushort_as_half((unsigned short)(rc >> 16)));
    float f  = ((g_mask[b >> 5] >> (b & 31)) & 1u) ? t.z : 0.0f;
    float2 v = vel[b];
    v.x = fmaf(f, t.x - ax, v.x);
    v.y = fmaf(f, t.y - ay, v.y);
    out[b] = v;
}

// ---------------------------------------------------------------------------
// Inputs: from_bodies, to_bodies, from_bodies_position, to_bodies_position,
//         stiffness, position, angle, mass, velocity
// ---------------------------------------------------------------------------
extern "C" void kernel_launch(void* const* d_in, const int* in_sizes, int n_in,
                              void* d_out, int out_size) {
    const int*    fromb = (const int*)   d_in[0];
    const int*    tob   = (const int*)   d_in[1];
    const float2* fpos  = (const float2*)d_in[2];
    const float2* tpos  = (const float2*)d_in[3];
    const float*  stiff = (const float*) d_in[4];
    const float2* pos   = (const float2*)d_in[5];
    const float*  ang   = (const float*) d_in[6];
    const float*  mass  = (const float*) d_in[7];
    const float2* vel   = (const float2*)d_in[8];

    int nc = in_sizes[0];
    int n  = in_sizes[6];
    if (n > NBODY) n = NBODY;

    const int tpb = 256;
    int work = (2 * nc > n) ? 2 * nc : n;    // KA covers bodies AND endpoints
    int nba  = (work + tpb - 1) / tpb;
    int nbb  = (n + tpb - 1) / tpb;          // = #partials (<= MAXPART)
    if (nbb > MAXPART) nbb = MAXPART;
    int half = n >> 1;
    int nb3  = (half + tpb - 1) / tpb;

    ka_build_scatter<<<nba, tpb>>>(pos, ang, fpos, tpos, fromb, tob, n, nc);
    kb_sums<<<nbb, tpb>>>(mass, n);
    kc_stage1<<<NS1, tpb>>>(nbb);
    kc_stage2<<<1, 32>>>(stiff);
    if (half > 0)
        k3_apply<<<nb3, tpb>>>((const float4*)vel, (float4*)d_out, half);
    if (n & 1)
        k3_apply_tail<<<1, tpb>>>(vel, (float2*)d_out, n - 1, n);
}

// round 17
// speedup vs baseline: 1.9459x; 1.9459x over previous
#include <cuda_runtime.h>
#include <cuda_fp16.h>

#define NBODY 4194304
#define MAXPART 16384
#define NS1 32
#define HALF_PI 1.57079632679489662f

// Scratch — __device__ globals. g_cnt is zero at load and re-zeroed by K2
// each call, so every graph replay starts from identical state.
__device__ unsigned int g_cnt[NBODY];    // per-body endpoint counts
__device__ unsigned int g_rec[NBODY];    // {f16 ax | (f16 ay, LSB=touched)}
__device__ float4       g_part[MAXPART]; // per-block partial sums {sx,sy,sm,0}
__device__ double4      g_p2[NS1];       // stage-1 reduced partials
__device__ float4       g_target;        // {tx, ty, stiffness*DT, 0}

// ---------------------------------------------------------------------------
// K1: pure count-scatter. int4 loads (4 constraints/thread), 8 fire-and-forget
// RED.ADD.u32 into spread addresses. (Verbatim from the 84.0 us build;
// measured at the L2 RMW data-path floor.)
// ---------------------------------------------------------------------------
__global__ void __launch_bounds__(256)
k1_scatter(const int4* __restrict__ fromb4,
           const int4* __restrict__ tob4,
           const int*  __restrict__ fromb,
           const int*  __restrict__ tob,
           int nc) {
    int i = blockIdx.x * blockDim.x + threadIdx.x;
    int n4 = nc >> 2;
    if (i < n4) {
        int4 a = fromb4[i];
        int4 b = tob4[i];
        atomicAdd(&g_cnt[a.x], 1u);
        atomicAdd(&g_cnt[a.y], 1u);
        atomicAdd(&g_cnt[a.z], 1u);
        atomicAdd(&g_cnt[a.w], 1u);
        atomicAdd(&g_cnt[b.x], 1u);
        atomicAdd(&g_cnt[b.y], 1u);
        atomicAdd(&g_cnt[b.z], 1u);
        atomicAdd(&g_cnt[b.w], 1u);
    } else {
        int j = (n4 << 2) + (i - n4);            // tail (nc % 4 elements)
        if (j < nc) {
            atomicAdd(&g_cnt[fromb[j]], 1u);
            atomicAdd(&g_cnt[tob[j]],   1u);
        }
    }
}

// ---------------------------------------------------------------------------
// K2: coalesced per-body pass, now 4 bodies/thread (uint4/float4 loads).
// Reads raw inputs once, reads+zeroes cnt, writes 4B records (touched flag in
// ay mantissa LSB), accumulates cnt*m*{ax,ay,1} into ONE plain float4 partial
// per block. No atomics. Same structure as the 84.0 us build, only wider.
// ---------------------------------------------------------------------------
__global__ void __launch_bounds__(256)
k2_sums(const float4* __restrict__ pos2,   // pairs of float2 positions
        const float4* __restrict__ ang4,   // 4 angles
        const float4* __restrict__ mass4,  // 4 masses
        const float2* __restrict__ fpos,
        const float2* __restrict__ tpos,
        int n, int nc) {
    int i  = blockIdx.x * blockDim.x + threadIdx.x;   // group of 4 bodies
    int b0 = 4 * i;

    float sx = 0.0f, sy = 0.0f, sm = 0.0f;

    if (b0 + 3 < n) {
        // fast path: full group of 4
        float4 pA = pos2[2 * i];          // bodies b0, b0+1
        float4 pB = pos2[2 * i + 1];      // bodies b0+2, b0+3
        float4 a4 = ang4[i];
        float4 m4 = mass4[i];

        // rel = concat(from_pos, to_pos) indexed by BODY index; pairs never
        // straddle the boundary (nc even), checked per pair.
        int p0 = 2 * i, p1 = 2 * i + 1;
        int nch = nc >> 1;
        float4 rA = (b0     < nc) ? ((const float4*)fpos)[p0]
                                  : ((const float4*)tpos)[p0 - nch];
        float4 rB = (b0 + 2 < nc) ? ((const float4*)fpos)[p1]
                                  : ((const float4*)tpos)[p1 - nch];

        uint4 cw = ((const uint4*)g_cnt)[i];
        ((uint4*)g_cnt)[i] = make_uint4(0u, 0u, 0u, 0u);  // replay state

        float s0, c0, s1, c1, s2, c2, s3, c3;
        __sincosf(a4.x - HALF_PI, &s0, &c0);
        __sincosf(a4.y - HALF_PI, &s1, &c1);
        __sincosf(a4.z - HALF_PI, &s2, &c2);
        __sincosf(a4.w - HALF_PI, &s3, &c3);

        float ax0 = fmaf(c0, rA.x, fmaf(-s0, rA.y, pA.x));
        float ay0 = fmaf(s0, rA.x, fmaf( c0, rA.y, pA.y));
        float ax1 = fmaf(c1, rA.z, fmaf(-s1, rA.w, pA.z));
        float ay1 = fmaf(s1, rA.z, fmaf( c1, rA.w, pA.w));
        float ax2 = fmaf(c2, rB.x, fmaf(-s2, rB.y, pB.x));
        float ay2 = fmaf(s2, rB.x, fmaf( c2, rB.y, pB.y));
        float ax3 = fmaf(c3, rB.z, fmaf(-s3, rB.w, pB.z));
        float ay3 = fmaf(s3, rB.z, fmaf( c3, rB.w, pB.w));

        unsigned int hx0 = (unsigned int)__half_as_ushort(__float2half_rn(ax0));
        unsigned int hy0 = (unsigned int)__half_as_ushort(__float2half_rn(ay0));
        unsigned int hx1 = (unsigned int)__half_as_ushort(__float2half_rn(ax1));
        unsigned int hy1 = (unsigned int)__half_as_ushort(__float2half_rn(ay1));
        unsigned int hx2 = (unsigned int)__half_as_ushort(__float2half_rn(ax2));
        unsigned int hy2 = (unsigned int)__half_as_ushort(__float2half_rn(ay2));
        unsigned int hx3 = (unsigned int)__half_as_ushort(__float2half_rn(ax3));
        unsigned int hy3 = (unsigned int)__half_as_ushort(__float2half_rn(ay3));
        hy0 = (hy0 & ~1u) | (cw.x != 0u ? 1u : 0u);   // touched flag in LSB
        hy1 = (hy1 & ~1u) | (cw.y != 0u ? 1u : 0u);
        hy2 = (hy2 & ~1u) | (cw.z != 0u ? 1u : 0u);
        hy3 = (hy3 & ~1u) | (cw.w != 0u ? 1u : 0u);
        ((uint4*)g_rec)[i] = make_uint4(hx0 | (hy0 << 16), hx1 | (hy1 << 16),
                                        hx2 | (hy2 << 16), hx3 | (hy3 << 16));

        float cm0 = (float)cw.x * m4.x;
        float cm1 = (float)cw.y * m4.y;
        float cm2 = (float)cw.z * m4.z;
        float cm3 = (float)cw.w * m4.w;
        sx = fmaf(cm0, ax0, fmaf(cm1, ax1, fmaf(cm2, ax2, cm3 * ax3)));
        sy = fmaf(cm0, ay0, fmaf(cm1, ay1, fmaf(cm2, ay2, cm3 * ay3)));
        sm = (cm0 + cm1) + (cm2 + cm3);
    } else if (b0 < n) {
        // scalar tail path (n % 4 != 0)
        const float2* posس = (const float2*)pos2;
        const float*  angs = (const float*)ang4;
        const float*  ms   = (const float*)mass4;
        for (int b = b0; b < n; ++b) {
            float2 p = posس[b];
            float  a = angs[b] - HALF_PI;
            float2 r = (b < nc) ? fpos[b] : tpos[b - nc];
            float s, c;
            __sincosf(a, &s, &c);
            float ax = fmaf(c, r.x, fmaf(-s, r.y, p.x));
            float ay = fmaf(s, r.x, fmaf( c, r.y, p.y));
            unsigned int cnt = g_cnt[b];
            g_cnt[b] = 0u;
            unsigned int hx = (unsigned int)__half_as_ushort(__float2half_rn(ax));
            unsigned int hy = (unsigned int)__half_as_ushort(__float2half_rn(ay));
            hy = (hy & ~1u) | (cnt != 0u ? 1u : 0u);
            g_rec[b] = hx | (hy << 16);
            float cm = (float)cnt * ms[b];
            sx = fmaf(cm, ax, sx);
            sy = fmaf(cm, ay, sy);
            sm += cm;
        }
    }

    #pragma unroll
    for (int o = 16; o > 0; o >>= 1) {
        sx += __shfl_down_sync(0xffffffffu, sx, o);
        sy += __shfl_down_sync(0xffffffffu, sy, o);
        sm += __shfl_down_sync(0xffffffffu, sm, o);
    }

    __shared__ float ssx[8], ssy[8], ssm[8];
    int wid = threadIdx.x >> 5, lid = threadIdx.x & 31;
    if (lid == 0) { ssx[wid] = sx; ssy[wid] = sy; ssm[wid] = sm; }
    __syncthreads();

    if (threadIdx.x == 0) {
        float tx = 0.0f, ty = 0.0f, tm = 0.0f;
        #pragma unroll
        for (int w = 0; w < 8; ++w) { tx += ssx[w]; ty += ssy[w]; tm += ssm[w]; }
        g_part[blockIdx.x] = make_float4(tx, ty, tm, 0.0f);   // plain store
    }
}

// ---------------------------------------------------------------------------
// K2b stage 1: 32 blocks x 256 threads reduce the partials in parallel.
// (Verbatim from the 84.0 us build.)
// ---------------------------------------------------------------------------
__global__ void __launch_bounds__(256)
k2b_stage1(int nparts) {
    int chunk = (nparts + NS1 - 1) / NS1;
    int base  = blockIdx.x * chunk;
    int end   = base + chunk; if (end > nparts) end = nparts;

    double sx = 0.0, sy = 0.0, sm = 0.0;
    for (int i = base + threadIdx.x; i < end; i += 256) {
        float4 p = g_part[i];
        sx += (double)p.x; sy += (double)p.y; sm += (double)p.z;
    }

    #pragma unroll
    for (int o = 16; o > 0; o >>= 1) {
        sx += __shfl_down_sync(0xffffffffu, sx, o);
        sy += __shfl_down_sync(0xffffffffu, sy, o);
        sm += __shfl_down_sync(0xffffffffu, sm, o);
    }
    __shared__ double dsx[8], dsy[8], dsm[8];
    int wid = threadIdx.x >> 5, lid = threadIdx.x & 31;
    if (lid == 0) { dsx[wid] = sx; dsy[wid] = sy; dsm[wid] = sm; }
    __syncthreads();
    if (threadIdx.x == 0) {
        double tx = 0.0, ty = 0.0, tm = 0.0;
        #pragma unroll
        for (int w = 0; w < 8; ++w) { tx += dsx[w]; ty += dsy[w]; tm += dsm[w]; }
        g_p2[blockIdx.x] = make_double4(tx, ty, tm, 0.0);
    }
}

// ---------------------------------------------------------------------------
// K2b stage 2: one warp reduces the 32 stage-1 partials and writes g_target.
// (Verbatim from the 84.0 us build.)
// ---------------------------------------------------------------------------
__global__ void __launch_bounds__(32)
k2b_stage2(const float* __restrict__ stiff) {
    int lid = threadIdx.x;
    double4 p = g_p2[lid];
    double sx = p.x, sy = p.y, sm = p.z;
    #pragma unroll
    for (int o = 16; o > 0; o >>= 1) {
        sx += __shfl_down_sync(0xffffffffu, sx, o);
        sy += __shfl_down_sync(0xffffffffu, sy, o);
        sm += __shfl_down_sync(0xffffffffu, sm, o);
    }
    if (lid == 0)
        g_target = make_float4((float)(sx / sm), (float)(sy / sm),
                               stiff[0] * 0.01f, 0.0f);
}

// ---------------------------------------------------------------------------
// K3: vectorized epilogue, 2 bodies/thread. (Verbatim from the 84.0 us build.)
// ---------------------------------------------------------------------------
__global__ void __launch_bounds__(256)
k3_apply(const float4* __restrict__ vel2,
         float4*       __restrict__ out2,
         int nhalf) {
    int i = blockIdx.x * blockDim.x + threadIdx.x;
    if (i >= nhalf) return;

    float4 t = g_target;                          // uniform broadcast
    uint2  rc = ((const uint2*)g_rec)[i];
    float4 v  = vel2[i];

    {
        float ax = __half2float(__ushort_as_half((unsigned short)(rc.x & 0xffffu)));
        unsigned int hy = rc.x >> 16;
        float ay = __half2float(__ushort_as_half((unsigned short)hy));
        float f  = (hy & 1u) ? t.z : 0.0f;
        v.x = fmaf(f, t.x - ax, v.x);
        v.y = fmaf(f, t.y - ay, v.y);
    }
    {
        float ax = __half2float(__ushort_as_half((unsigned short)(rc.y & 0xffffu)));
        unsigned int hy = rc.y >> 16;
        float ay = __half2float(__ushort_as_half((unsigned short)hy));
        float f  = (hy & 1u) ? t.z : 0.0f;
        v.z = fmaf(f, t.x - ax, v.z);
        v.w = fmaf(f, t.y - ay, v.w);
    }
    out2[i] = v;
}

__global__ void __launch_bounds__(256)
k3_apply_tail(const float2* __restrict__ vel,
              float2*       __restrict__ out,
              int start, int n) {
    int b = start + blockIdx.x * blockDim.x + threadIdx.x;
    if (b >= n) return;
    float4 t = g_target;
    unsigned int rc = g_rec[b];
    float ax = __half2float(__ushort_as_half((unsigned short)(rc & 0xffffu)));
    unsigned int hy = rc >> 16;
    float ay = __half2float(__ushort_as_half((unsigned short)hy));
    float f  = (hy & 1u) ? t.z : 0.0f;
    float2 v = vel[b];
    v.x = fmaf(f, t.x - ax, v.x);
    v.y = fmaf(f, t.y - ay, v.y);
    out[b] = v;
}

// ---------------------------------------------------------------------------
// Inputs: from_bodies, to_bodies, from_bodies_position, to_bodies_position,
//         stiffness, position, angle, mass, velocity
// ---------------------------------------------------------------------------
extern "C" void kernel_launch(void* const* d_in, const int* in_sizes, int n_in,
                              void* d_out, int out_size) {
    const int*    fromb = (const int*)   d_in[0];
    const int*    tob   = (const int*)   d_in[1];
    const float2* fpos  = (const float2*)d_in[2];
    const float2* tpos  = (const float2*)d_in[3];
    const float*  stiff = (const float*) d_in[4];
    const float2* pos   = (const float2*)d_in[5];
    const float*  ang   = (const float*) d_in[6];
    const float*  mass  = (const float*) d_in[7];
    const float2* vel   = (const float2*)d_in[8];

    int nc = in_sizes[0];
    int n  = in_sizes[6];
    if (n > NBODY) n = NBODY;

    const int tpb = 256;
    int n4    = nc >> 2;
    int k1t   = n4 + (nc & 3);
    int nb1   = (k1t + tpb - 1) / tpb;
    int nquad = (n + 3) >> 2;
    int nb2   = (nquad + tpb - 1) / tpb;
    if (nb2 > MAXPART) nb2 = MAXPART;             // n<=NBODY guarantees fit
    int half  = n >> 1;
    int nb3   = (half + tpb - 1) / tpb;

    k1_scatter<<<nb1, tpb>>>((const int4*)fromb, (const int4*)tob,
                             fromb, tob, nc);
    k2_sums<<<nb2, tpb>>>((const float4*)pos, (const float4*)ang,
                          (const float4*)mass, fpos, tpos, n, nc);
    k2b_stage1<<<NS1, tpb>>>(nb2);
    k2b_stage2<<<1, 32>>>(stiff);
    if (half > 0)
        k3_apply<<<nb3, tpb>>>((const float4*)vel, (float4*)d_out, half);
    if (n & 1)
        k3_apply_tail<<<1, tpb>>>(vel, (float2*)d_out, n - 1, n);
}